// round 7
// baseline (speedup 1.0000x reference)
#include <cuda_runtime.h>
#include <cstddef>
#include <cstdint>

// Problem constants
#define BB 8
#define TT 2048
#define DD 1024
#define HH 8
#define NN 32
#define MROWS (BB*TT)          // 16384
#define HN (HH*NN)             // 256

// ---------------------------------------------------------------------------
// Scratch (no cudaMalloc allowed) — __device__ globals.
// ---------------------------------------------------------------------------
__device__ float g_xp  [(size_t)MROWS * DD];   // 64 MB
__device__ float g_k   [(size_t)MROWS * HN];   // 16 MB
__device__ float g_v   [(size_t)MROWS * HN];
__device__ float g_q   [(size_t)MROWS * HN];
__device__ float g_beta[(size_t)MROWS * HN];
__device__ float g_cell[(size_t)MROWS * HN];

// ---------------------------------------------------------------------------
// bf16x2 split helpers (error-compensated tensor GEMM).
// ---------------------------------------------------------------------------
__device__ __forceinline__ float trunc_hi(float x) {
    return __uint_as_float(__float_as_uint(x) & 0xFFFF0000u);
}
__device__ __forceinline__ unsigned pack_hi_pair(float e0, float e1) {
    return __byte_perm(__float_as_uint(e0), __float_as_uint(e1), 0x7632);
}
__device__ __forceinline__ unsigned pack_lo_pair(float l0, float l1) {
    unsigned d;
    asm("cvt.rn.bf16x2.f32 %0, %1, %2;" : "=r"(d) : "f"(l1), "f"(l0));
    return d;
}

__device__ __forceinline__ void mma_bf16(float d[4],
                                         unsigned a0, unsigned a1,
                                         unsigned a2, unsigned a3,
                                         unsigned b0, unsigned b1) {
    asm("mma.sync.aligned.m16n8k16.row.col.f32.bf16.bf16.f32 "
        "{%0,%1,%2,%3}, {%4,%5,%6,%7}, {%8,%9}, {%0,%1,%2,%3};"
        : "+f"(d[0]), "+f"(d[1]), "+f"(d[2]), "+f"(d[3])
        : "r"(a0), "r"(a1), "r"(a2), "r"(a3), "r"(b0), "r"(b1));
}

// ---------------------------------------------------------------------------
// bf16x2-compensated tensor-core GEMM (unchanged from round 6).
// C[M,Nout] = epi( A[M,K] @ W[Nout,K]^T ), block 128x128, BK=16, 8 warps.
// epi: 0 identity, 1 silu, 2 sigmoid(acc + bias[col])
// ---------------------------------------------------------------------------
#define PLW 12
#define PLANE (128 * PLW)

__device__ __forceinline__ void stage8(const float* __restrict__ gp,
                                       unsigned* __restrict__ hi,
                                       unsigned* __restrict__ lo) {
    float4 x0 = *reinterpret_cast<const float4*>(gp);
    float4 x1 = *reinterpret_cast<const float4*>(gp + 4);
    hi[0] = pack_hi_pair(x0.x, x0.y);
    hi[1] = pack_hi_pair(x0.z, x0.w);
    hi[2] = pack_hi_pair(x1.x, x1.y);
    hi[3] = pack_hi_pair(x1.z, x1.w);
    lo[0] = pack_lo_pair(x0.x - trunc_hi(x0.x), x0.y - trunc_hi(x0.y));
    lo[1] = pack_lo_pair(x0.z - trunc_hi(x0.z), x0.w - trunc_hi(x0.w));
    lo[2] = pack_lo_pair(x1.x - trunc_hi(x1.x), x1.y - trunc_hi(x1.y));
    lo[3] = pack_lo_pair(x1.z - trunc_hi(x1.z), x1.w - trunc_hi(x1.w));
}

__device__ __forceinline__ void mma_gemm_core(
    const float* __restrict__ A, const float* __restrict__ W,
    float* __restrict__ C, const float* __restrict__ bias,
    int epi, int Nout, int K, int row0, int col0)
{
    __shared__ unsigned sm[2][4 * PLANE];

    const int tid  = threadIdx.x;
    const int wid  = tid >> 5;
    const int lane = tid & 31;
    const int g    = lane >> 2;
    const int c    = lane & 3;
    const int wm   = (wid & 1) * 64;
    const int wn   = (wid >> 1) * 32;

    const int lr = tid >> 1;
    const int le = (tid & 1) * 8;
    const int wb = (tid & 1) * 4;
    const float* Ap = A + (size_t)(row0 + lr) * K + le;
    const float* Wp = W + (size_t)(col0 + lr) * K + le;
    const int srow = lr * PLW + wb;

    float acc[4][4][4];
#pragma unroll
    for (int mt = 0; mt < 4; ++mt)
#pragma unroll
        for (int nt = 0; nt < 4; ++nt)
#pragma unroll
            for (int e = 0; e < 4; ++e) acc[mt][nt][e] = 0.f;

    const int nchunks = K / 16;

    stage8(Ap, &sm[0][0 * PLANE + srow], &sm[0][1 * PLANE + srow]);
    stage8(Wp, &sm[0][2 * PLANE + srow], &sm[0][3 * PLANE + srow]);
    __syncthreads();

    for (int chunk = 0; chunk < nchunks; ++chunk) {
        const int cur = chunk & 1;
        const bool more = (chunk + 1 < nchunks);

        float4 pa0, pa1, pw0, pw1;
        if (more) {
            const int ko = (chunk + 1) * 16;
            pa0 = *reinterpret_cast<const float4*>(Ap + ko);
            pa1 = *reinterpret_cast<const float4*>(Ap + ko + 4);
            pw0 = *reinterpret_cast<const float4*>(Wp + ko);
            pw1 = *reinterpret_cast<const float4*>(Wp + ko + 4);
        }

        const unsigned* Ahi = &sm[cur][0 * PLANE];
        const unsigned* Alo = &sm[cur][1 * PLANE];
        const unsigned* Whi = &sm[cur][2 * PLANE];
        const unsigned* Wlo = &sm[cur][3 * PLANE];

#pragma unroll
        for (int mh = 0; mh < 2; ++mh) {
            unsigned ah[2][4], al[2][4];
#pragma unroll
            for (int m2 = 0; m2 < 2; ++m2) {
                const int rb = wm + (mh * 2 + m2) * 16;
                const int r0 = (rb + g) * PLW;
                const int r1 = (rb + 8 + g) * PLW;
                ah[m2][0] = Ahi[r0 + c];     ah[m2][1] = Ahi[r1 + c];
                ah[m2][2] = Ahi[r0 + 4 + c]; ah[m2][3] = Ahi[r1 + 4 + c];
                al[m2][0] = Alo[r0 + c];     al[m2][1] = Alo[r1 + c];
                al[m2][2] = Alo[r0 + 4 + c]; al[m2][3] = Alo[r1 + 4 + c];
            }
#pragma unroll
            for (int nt = 0; nt < 4; ++nt) {
                const int wr = (wn + nt * 8 + g) * PLW;
                const unsigned bh0 = Whi[wr + c];
                const unsigned bh1 = Whi[wr + 4 + c];
                const unsigned bl0 = Wlo[wr + c];
                const unsigned bl1 = Wlo[wr + 4 + c];
#pragma unroll
                for (int m2 = 0; m2 < 2; ++m2) {
                    float* d = acc[mh * 2 + m2][nt];
                    mma_bf16(d, ah[m2][0], ah[m2][1], ah[m2][2], ah[m2][3], bh0, bh1);
                    mma_bf16(d, al[m2][0], al[m2][1], al[m2][2], al[m2][3], bh0, bh1);
                    mma_bf16(d, ah[m2][0], ah[m2][1], ah[m2][2], ah[m2][3], bl0, bl1);
                }
            }
        }

        if (more) {
            const int nxt = cur ^ 1;
            float4 t;
            unsigned* ahd = &sm[nxt][0 * PLANE + srow];
            unsigned* ald = &sm[nxt][1 * PLANE + srow];
            unsigned* whd = &sm[nxt][2 * PLANE + srow];
            unsigned* wld = &sm[nxt][3 * PLANE + srow];
            t = pa0;
            ahd[0] = pack_hi_pair(t.x, t.y); ahd[1] = pack_hi_pair(t.z, t.w);
            ald[0] = pack_lo_pair(t.x - trunc_hi(t.x), t.y - trunc_hi(t.y));
            ald[1] = pack_lo_pair(t.z - trunc_hi(t.z), t.w - trunc_hi(t.w));
            t = pa1;
            ahd[2] = pack_hi_pair(t.x, t.y); ahd[3] = pack_hi_pair(t.z, t.w);
            ald[2] = pack_lo_pair(t.x - trunc_hi(t.x), t.y - trunc_hi(t.y));
            ald[3] = pack_lo_pair(t.z - trunc_hi(t.z), t.w - trunc_hi(t.w));
            t = pw0;
            whd[0] = pack_hi_pair(t.x, t.y); whd[1] = pack_hi_pair(t.z, t.w);
            wld[0] = pack_lo_pair(t.x - trunc_hi(t.x), t.y - trunc_hi(t.y));
            wld[1] = pack_lo_pair(t.z - trunc_hi(t.z), t.w - trunc_hi(t.w));
            t = pw1;
            whd[2] = pack_hi_pair(t.x, t.y); whd[3] = pack_hi_pair(t.z, t.w);
            wld[2] = pack_lo_pair(t.x - trunc_hi(t.x), t.y - trunc_hi(t.y));
            wld[3] = pack_lo_pair(t.z - trunc_hi(t.z), t.w - trunc_hi(t.w));
        }
        __syncthreads();
    }

#pragma unroll
    for (int mt = 0; mt < 4; ++mt) {
        const int r0 = row0 + wm + mt * 16 + g;
#pragma unroll
        for (int nt = 0; nt < 4; ++nt) {
            const int cc = col0 + wn + nt * 8 + 2 * c;
            float d0 = acc[mt][nt][0], d1 = acc[mt][nt][1];
            float d2 = acc[mt][nt][2], d3 = acc[mt][nt][3];
            if (epi == 1) {
                d0 = d0 / (1.f + __expf(-d0));
                d1 = d1 / (1.f + __expf(-d1));
                d2 = d2 / (1.f + __expf(-d2));
                d3 = d3 / (1.f + __expf(-d3));
            } else if (epi == 2) {
                const float b0 = bias[cc], b1 = bias[cc + 1];
                d0 = 1.f / (1.f + __expf(-(d0 + b0)));
                d1 = 1.f / (1.f + __expf(-(d1 + b1)));
                d2 = 1.f / (1.f + __expf(-(d2 + b0)));
                d3 = 1.f / (1.f + __expf(-(d3 + b1)));
            }
            *reinterpret_cast<float2*>(C + (size_t)r0 * Nout + cc)       = make_float2(d0, d1);
            *reinterpret_cast<float2*>(C + (size_t)(r0 + 8) * Nout + cc) = make_float2(d2, d3);
        }
    }
}

template<int EPI>
__global__ void __launch_bounds__(256, 2)
gemm_awt(const float* __restrict__ A, const float* __restrict__ W,
         float* __restrict__ C, const float* __restrict__ bias,
         int Nout, int K)
{
    mma_gemm_core(A, W, C, bias, EPI, Nout, K, blockIdx.y * 128, blockIdx.x * 128);
}

struct ProjPtrs {
    const float* W[4];
    float*       C[4];
};

__global__ void __launch_bounds__(256, 2)
gemm_proj4(const float* __restrict__ A, ProjPtrs p, const float* __restrict__ bias,
           int Nout, int K)
{
    const int z = blockIdx.z;
    mma_gemm_core(A, p.W[z], p.C[z], bias, (z == 3) ? 2 : 0, Nout, K,
                  blockIdx.y * 128, blockIdx.x * 128);
}

// ---------------------------------------------------------------------------
// k-normalization (in place): kn = k / (||k|| + 1e-6), one warp per 32-vector.
// ---------------------------------------------------------------------------
__global__ void __launch_bounds__(256)
knorm_kernel(float* __restrict__ kk)
{
    const size_t r = (size_t)blockIdx.x * 8 + (threadIdx.x >> 5);
    const int j = threadIdx.x & 31;
    const size_t a = r * 32 + j;
    const float v = kk[a];
    float s2 = v * v;
#pragma unroll
    for (int o = 16; o > 0; o >>= 1) s2 += __shfl_xor_sync(0xffffffffu, s2, o);
    kk[a] = v / (sqrtf(s2) + 1e-6f);
}

// ---------------------------------------------------------------------------
// Sequential scan, re-tiled: ONE BLOCK (128 threads) per chain, 64 blocks.
// Warp w owns rows w*8..w*8+7. Lane l: row i = w*8 + (l>>2),
// cols j = (l&3)*8 .. +7 (8 state elements in registers).
// Row reduction = 8-wide in-register fma tree + 2 shfl levels (xor 1, 2).
// Only 4 shfls per warp-step (vs 22 before) -> off the MIO throughput wall.
// One warp per SMSP (64 blocks over 148 SMs) -> private scheduler slot.
// ---------------------------------------------------------------------------
#define SPF 2

__device__ __forceinline__ float tree8(const float* __restrict__ a,
                                       const float* __restrict__ b) {
    float t0 = fmaf(a[1], b[1], a[0] * b[0]);
    float t1 = fmaf(a[3], b[3], a[2] * b[2]);
    float t2 = fmaf(a[5], b[5], a[4] * b[4]);
    float t3 = fmaf(a[7], b[7], a[6] * b[6]);
    return (t0 + t1) + (t2 + t3);
}

__global__ void __launch_bounds__(128)
scan_kernel(const float* __restrict__ Kn, const float* __restrict__ Vp,
            const float* __restrict__ Qp, const float* __restrict__ Bp,
            float* __restrict__ cell, float* __restrict__ S_final, int writeS)
{
    const int chain = blockIdx.x;          // 0..63
    const int w  = threadIdx.x >> 5;       // warp 0..3
    const int l  = threadIdx.x & 31;
    const int i  = w * 8 + (l >> 2);       // state row 0..31
    const int j0 = (l & 3) * 8;            // first state col of this lane
    const size_t cb = ((size_t)(chain >> 3) * TT) * HN + (size_t)(chain & 7) * NN;

    float S[8];
#pragma unroll
    for (int c = 0; c < 8; ++c) S[c] = 0.f;

    // prefetch ring (depth SPF)
    float4 pk0[SPF], pk1[SPF], pq0[SPF], pq1[SPF];
    float pv[SPF], pb[SPF];
#pragma unroll
    for (int d = 0; d < SPF; ++d) {
        const size_t a = cb + (size_t)d * HN;
        pk0[d] = *reinterpret_cast<const float4*>(Kn + a + j0);
        pk1[d] = *reinterpret_cast<const float4*>(Kn + a + j0 + 4);
        pq0[d] = *reinterpret_cast<const float4*>(Qp + a + j0);
        pq1[d] = *reinterpret_cast<const float4*>(Qp + a + j0 + 4);
        pv[d]  = Vp[a + i];
        pb[d]  = Bp[a + i];
    }

    size_t base = cb;
    for (int t = 0; t < TT; t += SPF) {
#pragma unroll
        for (int u = 0; u < SPF; ++u) {
            // prefetch step t+u+SPF
            const int tp = t + u + SPF;
            const size_t pa = cb + (size_t)((tp < TT) ? tp : (TT - 1)) * HN;
            const float4 nk0 = *reinterpret_cast<const float4*>(Kn + pa + j0);
            const float4 nk1 = *reinterpret_cast<const float4*>(Kn + pa + j0 + 4);
            const float4 nq0 = *reinterpret_cast<const float4*>(Qp + pa + j0);
            const float4 nq1 = *reinterpret_cast<const float4*>(Qp + pa + j0 + 4);
            const float  nv  = Vp[pa + i];
            const float  nb  = Bp[pa + i];

            const float kr[8] = {pk0[u].x, pk0[u].y, pk0[u].z, pk0[u].w,
                                 pk1[u].x, pk1[u].y, pk1[u].z, pk1[u].w};
            const float qr[8] = {pq0[u].x, pq0[u].y, pq0[u].z, pq0[u].w,
                                 pq1[u].x, pq1[u].y, pq1[u].z, pq1[u].w};

            // retrieved_i = sum_j S_ij*kn_j : 8-wide reg tree + 2 shfl levels
            float r = tree8(S, kr);
            r += __shfl_xor_sync(0xffffffffu, r, 1);
            r += __shfl_xor_sync(0xffffffffu, r, 2);

            const float delta = pv[u] - r;
            const float bi    = pb[u];

            // S_ij = tanh(bi*S + delta*kn_j)  (8 independent tanh, pipelined MUFU)
#pragma unroll
            for (int c = 0; c < 8; ++c) {
                const float z = fmaf(bi, S[c], delta * kr[c]);
                const float e = __expf(2.f * z);
                S[c] = 1.f - __fdividef(2.f, e + 1.f);
            }

            // output: Sq_i then out = Sq^2 * sigmoid(Sq)
            float sq = tree8(S, qr);
            sq += __shfl_xor_sync(0xffffffffu, sq, 1);
            sq += __shfl_xor_sync(0xffffffffu, sq, 2);
            if ((l & 3) == 0)
                cell[base + i] = sq * sq * __fdividef(1.f, 1.f + __expf(-sq));

            pk0[u] = nk0; pk1[u] = nk1; pq0[u] = nq0; pq1[u] = nq1;
            pv[u] = nv;   pb[u] = nb;
            base += HN;
        }
    }

    if (writeS) {
#pragma unroll
        for (int c = 0; c < 8; ++c)
            S_final[((size_t)chain * NN + i) * NN + j0 + c] = S[c];
    }
}

// ---------------------------------------------------------------------------
// Host launcher
// ---------------------------------------------------------------------------
extern "C" void kernel_launch(void* const* d_in, const int* in_sizes, int n_in,
                              void* d_out, int out_size)
{
    const float* x      = (const float*)d_in[0];
    const float* W_in   = (const float*)d_in[1];
    const float* W_k    = (const float*)d_in[2];
    const float* W_v    = (const float*)d_in[3];
    const float* W_q    = (const float*)d_in[4];
    const float* W_beta = (const float*)d_in[5];
    const float* b_beta = (const float*)d_in[6];
    const float* W_out  = (const float*)d_in[7];
    float* y = (float*)d_out;

    float *xp, *k, *v, *q, *bt, *cell;
    cudaGetSymbolAddress((void**)&xp,   g_xp);
    cudaGetSymbolAddress((void**)&k,    g_k);
    cudaGetSymbolAddress((void**)&v,    g_v);
    cudaGetSymbolAddress((void**)&q,    g_q);
    cudaGetSymbolAddress((void**)&bt,   g_beta);
    cudaGetSymbolAddress((void**)&cell, g_cell);

    const int M = MROWS;

    // 1. xp = silu(x @ W_in^T)
    gemm_awt<1><<<dim3(DD / 128, M / 128), 256>>>(x, W_in, xp, nullptr, DD, DD);

    // 2. fused projections (k, v, q, beta)
    ProjPtrs p;
    p.W[0] = W_k;  p.W[1] = W_v;  p.W[2] = W_q;  p.W[3] = W_beta;
    p.C[0] = k;    p.C[1] = v;    p.C[2] = q;    p.C[3] = bt;
    gemm_proj4<<<dim3(HN / 128, M / 128, 4), 256>>>(xp, p, b_beta, HN, DD);

    // 3. normalize k in place
    knorm_kernel<<<(MROWS * HH) / 8, 256>>>(k);

    // 4. sequential scan (one block per chain)
    const size_t y_elems = (size_t)M * DD;
    const int writeS = (out_size >= (int)(y_elems + (size_t)BB * HH * NN * NN)) ? 1 : 0;
    scan_kernel<<<BB * HH, 128>>>(k, v, q, bt, cell, y + y_elems, writeS);

    // 5. y = cell @ W_out^T
    gemm_awt<0><<<dim3(DD / 128, M / 128), 256>>>(cell, W_out, y, nullptr, DD, HN);
}

// round 8
// speedup vs baseline: 1.3411x; 1.3411x over previous
#include <cuda_runtime.h>
#include <cstddef>
#include <cstdint>

// Problem constants
#define BB 8
#define TT 2048
#define DD 1024
#define HH 8
#define NN 32
#define MROWS (BB*TT)          // 16384
#define HN (HH*NN)             // 256

// ---------------------------------------------------------------------------
// Scratch (no cudaMalloc allowed) — __device__ globals.
// ---------------------------------------------------------------------------
__device__ float g_xp  [(size_t)MROWS * DD];   // 64 MB
__device__ float g_k   [(size_t)MROWS * HN];   // 16 MB
__device__ float g_v   [(size_t)MROWS * HN];
__device__ float g_q   [(size_t)MROWS * HN];
__device__ float g_beta[(size_t)MROWS * HN];
__device__ float g_cell[(size_t)MROWS * HN];

// ---------------------------------------------------------------------------
// bf16x2 split helpers (error-compensated tensor GEMM).
// ---------------------------------------------------------------------------
__device__ __forceinline__ float trunc_hi(float x) {
    return __uint_as_float(__float_as_uint(x) & 0xFFFF0000u);
}
__device__ __forceinline__ unsigned pack_hi_pair(float e0, float e1) {
    return __byte_perm(__float_as_uint(e0), __float_as_uint(e1), 0x7632);
}
__device__ __forceinline__ unsigned pack_lo_pair(float l0, float l1) {
    unsigned d;
    asm("cvt.rn.bf16x2.f32 %0, %1, %2;" : "=r"(d) : "f"(l1), "f"(l0));
    return d;
}

__device__ __forceinline__ void mma_bf16(float d[4],
                                         unsigned a0, unsigned a1,
                                         unsigned a2, unsigned a3,
                                         unsigned b0, unsigned b1) {
    asm("mma.sync.aligned.m16n8k16.row.col.f32.bf16.bf16.f32 "
        "{%0,%1,%2,%3}, {%4,%5,%6,%7}, {%8,%9}, {%0,%1,%2,%3};"
        : "+f"(d[0]), "+f"(d[1]), "+f"(d[2]), "+f"(d[3])
        : "r"(a0), "r"(a1), "r"(a2), "r"(a3), "r"(b0), "r"(b1));
}

// ---------------------------------------------------------------------------
// bf16x2-compensated tensor-core GEMM.
// C[M,Nout] = epi( A[M,K] @ W[Nout,K]^T ), block 128x128, BK=16, 8 warps.
// epi: 0 identity, 1 silu, 2 sigmoid(acc + bias[col]),
//      3 row-normalize per 32-col head band (k-projection)
// ---------------------------------------------------------------------------
#define PLW 12
#define PLANE (128 * PLW)

__device__ __forceinline__ void stage8(const float* __restrict__ gp,
                                       unsigned* __restrict__ hi,
                                       unsigned* __restrict__ lo) {
    float4 x0 = *reinterpret_cast<const float4*>(gp);
    float4 x1 = *reinterpret_cast<const float4*>(gp + 4);
    hi[0] = pack_hi_pair(x0.x, x0.y);
    hi[1] = pack_hi_pair(x0.z, x0.w);
    hi[2] = pack_hi_pair(x1.x, x1.y);
    hi[3] = pack_hi_pair(x1.z, x1.w);
    lo[0] = pack_lo_pair(x0.x - trunc_hi(x0.x), x0.y - trunc_hi(x0.y));
    lo[1] = pack_lo_pair(x0.z - trunc_hi(x0.z), x0.w - trunc_hi(x0.w));
    lo[2] = pack_lo_pair(x1.x - trunc_hi(x1.x), x1.y - trunc_hi(x1.y));
    lo[3] = pack_lo_pair(x1.z - trunc_hi(x1.z), x1.w - trunc_hi(x1.w));
}

__device__ __forceinline__ void mma_gemm_core(
    const float* __restrict__ A, const float* __restrict__ W,
    float* __restrict__ C, const float* __restrict__ bias,
    int epi, int Nout, int K, int row0, int col0)
{
    __shared__ unsigned sm[2][4 * PLANE];

    const int tid  = threadIdx.x;
    const int wid  = tid >> 5;
    const int lane = tid & 31;
    const int g    = lane >> 2;
    const int c    = lane & 3;
    const int wm   = (wid & 1) * 64;
    const int wn   = (wid >> 1) * 32;

    const int lr = tid >> 1;
    const int le = (tid & 1) * 8;
    const int wb = (tid & 1) * 4;
    const float* Ap = A + (size_t)(row0 + lr) * K + le;
    const float* Wp = W + (size_t)(col0 + lr) * K + le;
    const int srow = lr * PLW + wb;

    float acc[4][4][4];
#pragma unroll
    for (int mt = 0; mt < 4; ++mt)
#pragma unroll
        for (int nt = 0; nt < 4; ++nt)
#pragma unroll
            for (int e = 0; e < 4; ++e) acc[mt][nt][e] = 0.f;

    const int nchunks = K / 16;

    stage8(Ap, &sm[0][0 * PLANE + srow], &sm[0][1 * PLANE + srow]);
    stage8(Wp, &sm[0][2 * PLANE + srow], &sm[0][3 * PLANE + srow]);
    __syncthreads();

    for (int chunk = 0; chunk < nchunks; ++chunk) {
        const int cur = chunk & 1;
        const bool more = (chunk + 1 < nchunks);

        float4 pa0, pa1, pw0, pw1;
        if (more) {
            const int ko = (chunk + 1) * 16;
            pa0 = *reinterpret_cast<const float4*>(Ap + ko);
            pa1 = *reinterpret_cast<const float4*>(Ap + ko + 4);
            pw0 = *reinterpret_cast<const float4*>(Wp + ko);
            pw1 = *reinterpret_cast<const float4*>(Wp + ko + 4);
        }

        const unsigned* Ahi = &sm[cur][0 * PLANE];
        const unsigned* Alo = &sm[cur][1 * PLANE];
        const unsigned* Whi = &sm[cur][2 * PLANE];
        const unsigned* Wlo = &sm[cur][3 * PLANE];

#pragma unroll
        for (int mh = 0; mh < 2; ++mh) {
            unsigned ah[2][4], al[2][4];
#pragma unroll
            for (int m2 = 0; m2 < 2; ++m2) {
                const int rb = wm + (mh * 2 + m2) * 16;
                const int r0 = (rb + g) * PLW;
                const int r1 = (rb + 8 + g) * PLW;
                ah[m2][0] = Ahi[r0 + c];     ah[m2][1] = Ahi[r1 + c];
                ah[m2][2] = Ahi[r0 + 4 + c]; ah[m2][3] = Ahi[r1 + 4 + c];
                al[m2][0] = Alo[r0 + c];     al[m2][1] = Alo[r1 + c];
                al[m2][2] = Alo[r0 + 4 + c]; al[m2][3] = Alo[r1 + 4 + c];
            }
#pragma unroll
            for (int nt = 0; nt < 4; ++nt) {
                const int wr = (wn + nt * 8 + g) * PLW;
                const unsigned bh0 = Whi[wr + c];
                const unsigned bh1 = Whi[wr + 4 + c];
                const unsigned bl0 = Wlo[wr + c];
                const unsigned bl1 = Wlo[wr + 4 + c];
#pragma unroll
                for (int m2 = 0; m2 < 2; ++m2) {
                    float* d = acc[mh * 2 + m2][nt];
                    mma_bf16(d, ah[m2][0], ah[m2][1], ah[m2][2], ah[m2][3], bh0, bh1);
                    mma_bf16(d, al[m2][0], al[m2][1], al[m2][2], al[m2][3], bh0, bh1);
                    mma_bf16(d, ah[m2][0], ah[m2][1], ah[m2][2], ah[m2][3], bl0, bl1);
                }
            }
        }

        if (more) {
            const int nxt = cur ^ 1;
            float4 t;
            unsigned* ahd = &sm[nxt][0 * PLANE + srow];
            unsigned* ald = &sm[nxt][1 * PLANE + srow];
            unsigned* whd = &sm[nxt][2 * PLANE + srow];
            unsigned* wld = &sm[nxt][3 * PLANE + srow];
            t = pa0;
            ahd[0] = pack_hi_pair(t.x, t.y); ahd[1] = pack_hi_pair(t.z, t.w);
            ald[0] = pack_lo_pair(t.x - trunc_hi(t.x), t.y - trunc_hi(t.y));
            ald[1] = pack_lo_pair(t.z - trunc_hi(t.z), t.w - trunc_hi(t.w));
            t = pa1;
            ahd[2] = pack_hi_pair(t.x, t.y); ahd[3] = pack_hi_pair(t.z, t.w);
            ald[2] = pack_lo_pair(t.x - trunc_hi(t.x), t.y - trunc_hi(t.y));
            ald[3] = pack_lo_pair(t.z - trunc_hi(t.z), t.w - trunc_hi(t.w));
            t = pw0;
            whd[0] = pack_hi_pair(t.x, t.y); whd[1] = pack_hi_pair(t.z, t.w);
            wld[0] = pack_lo_pair(t.x - trunc_hi(t.x), t.y - trunc_hi(t.y));
            wld[1] = pack_lo_pair(t.z - trunc_hi(t.z), t.w - trunc_hi(t.w));
            t = pw1;
            whd[2] = pack_hi_pair(t.x, t.y); whd[3] = pack_hi_pair(t.z, t.w);
            wld[2] = pack_lo_pair(t.x - trunc_hi(t.x), t.y - trunc_hi(t.y));
            wld[3] = pack_lo_pair(t.z - trunc_hi(t.z), t.w - trunc_hi(t.w));
        }
        __syncthreads();
    }

    if (epi == 3) {
        // k-projection epilogue: normalize each row's 32-col head band.
        // Warp band [wn, wn+32) is exactly one head. Row values live in
        // acc[mt][0..3][{0,1}] (row r0) and acc[mt][0..3][{2,3}] (row r0+8),
        // spread over lanes c=0..3 of the same g.
#pragma unroll
        for (int mt = 0; mt < 4; ++mt) {
            float se = 0.f, so = 0.f;
#pragma unroll
            for (int nt = 0; nt < 4; ++nt) {
                se = fmaf(acc[mt][nt][0], acc[mt][nt][0], se);
                se = fmaf(acc[mt][nt][1], acc[mt][nt][1], se);
                so = fmaf(acc[mt][nt][2], acc[mt][nt][2], so);
                so = fmaf(acc[mt][nt][3], acc[mt][nt][3], so);
            }
            se += __shfl_xor_sync(0xffffffffu, se, 1);
            se += __shfl_xor_sync(0xffffffffu, se, 2);
            so += __shfl_xor_sync(0xffffffffu, so, 1);
            so += __shfl_xor_sync(0xffffffffu, so, 2);
            const float ie = __fdividef(1.f, sqrtf(se) + 1e-6f);
            const float io = __fdividef(1.f, sqrtf(so) + 1e-6f);
            const int r0 = row0 + wm + mt * 16 + g;
#pragma unroll
            for (int nt = 0; nt < 4; ++nt) {
                const int cc = col0 + wn + nt * 8 + 2 * c;
                *reinterpret_cast<float2*>(C + (size_t)r0 * Nout + cc) =
                    make_float2(acc[mt][nt][0] * ie, acc[mt][nt][1] * ie);
                *reinterpret_cast<float2*>(C + (size_t)(r0 + 8) * Nout + cc) =
                    make_float2(acc[mt][nt][2] * io, acc[mt][nt][3] * io);
            }
        }
        return;
    }

#pragma unroll
    for (int mt = 0; mt < 4; ++mt) {
        const int r0 = row0 + wm + mt * 16 + g;
#pragma unroll
        for (int nt = 0; nt < 4; ++nt) {
            const int cc = col0 + wn + nt * 8 + 2 * c;
            float d0 = acc[mt][nt][0], d1 = acc[mt][nt][1];
            float d2 = acc[mt][nt][2], d3 = acc[mt][nt][3];
            if (epi == 1) {
                d0 = d0 * __fdividef(1.f, 1.f + __expf(-d0));
                d1 = d1 * __fdividef(1.f, 1.f + __expf(-d1));
                d2 = d2 * __fdividef(1.f, 1.f + __expf(-d2));
                d3 = d3 * __fdividef(1.f, 1.f + __expf(-d3));
            } else if (epi == 2) {
                const float b0 = bias[cc], b1 = bias[cc + 1];
                d0 = __fdividef(1.f, 1.f + __expf(-(d0 + b0)));
                d1 = __fdividef(1.f, 1.f + __expf(-(d1 + b1)));
                d2 = __fdividef(1.f, 1.f + __expf(-(d2 + b0)));
                d3 = __fdividef(1.f, 1.f + __expf(-(d3 + b1)));
            }
            *reinterpret_cast<float2*>(C + (size_t)r0 * Nout + cc)       = make_float2(d0, d1);
            *reinterpret_cast<float2*>(C + (size_t)(r0 + 8) * Nout + cc) = make_float2(d2, d3);
        }
    }
}

template<int EPI>
__global__ void __launch_bounds__(256, 2)
gemm_awt(const float* __restrict__ A, const float* __restrict__ W,
         float* __restrict__ C, const float* __restrict__ bias,
         int Nout, int K)
{
    mma_gemm_core(A, W, C, bias, EPI, Nout, K, blockIdx.y * 128, blockIdx.x * 128);
}

struct ProjPtrs {
    const float* W[4];
    float*       C[4];
};

// z: 0 = k (normalize), 1 = v, 2 = q, 3 = beta (sigmoid+bias)
__global__ void __launch_bounds__(256, 2)
gemm_proj4(const float* __restrict__ A, ProjPtrs p, const float* __restrict__ bias,
           int Nout, int K)
{
    const int z = blockIdx.z;
    const int epi = (z == 0) ? 3 : ((z == 3) ? 2 : 0);
    mma_gemm_core(A, p.W[z], p.C[z], bias, epi, Nout, K,
                  blockIdx.y * 128, blockIdx.x * 128);
}

// ---------------------------------------------------------------------------
// Barrier-free sequential scan, tiling: 2 cols/lane, 2 rows/warp,
// 16 warps/chain (1024 warps total, ~1.7/SMSP).
//  - lane l: row i = wc*2 + (l>>4), cols (l&15)*2, (l&15)*2+1
//  - reduction: 1 in-reg fma + 4 shfl levels (xor 1,2,4,8 within 16-lane half)
//  - deferred S·q: previous step's output reduction interleaved with current
//    step's S·kn butterfly
//  - 2 tanh per thread (4 MUFU warp-instrs, under rt wall)
//  - prefetch ring depth 4, float2 loads for k/q
// ---------------------------------------------------------------------------
#define PF 4

__global__ void __launch_bounds__(128)
scan_kernel(const float* __restrict__ Kn, const float* __restrict__ Vp,
            const float* __restrict__ Qp, const float* __restrict__ Bp,
            float* __restrict__ cell, float* __restrict__ S_final, int writeS)
{
    const int g     = blockIdx.x * 4 + (threadIdx.x >> 5);  // global warp 0..1023
    const int chain = g >> 4;                // 0..63
    const int wc    = g & 15;                // warp-in-chain 0..15
    const int l     = threadIdx.x & 31;
    const int i     = wc * 2 + (l >> 4);     // state row 0..31
    const int j0    = (l & 15) * 2;          // first state col of this lane
    const size_t cb = ((size_t)(chain >> 3) * TT) * HN + (size_t)(chain & 7) * NN;

    float2 pk[PF], pq[PF];
    float  pv[PF], pb[PF];
#pragma unroll
    for (int d = 0; d < PF; ++d) {
        const size_t a = cb + (size_t)d * HN;
        pk[d] = *reinterpret_cast<const float2*>(Kn + a + j0);
        pq[d] = *reinterpret_cast<const float2*>(Qp + a + j0);
        pv[d] = Vp[a + i];
        pb[d] = Bp[a + i];
    }

    float S0 = 0.f, S1 = 0.f, sqp = 0.f;   // sqp: pending S·q partial
    size_t base = cb;

    for (int t = 0; t < TT; t += PF) {
#pragma unroll
        for (int u = 0; u < PF; ++u) {
            const int tcur = t + u;
            const int tpre = (tcur + PF < TT) ? (tcur + PF) : (TT - 1);
            const size_t pa = cb + (size_t)tpre * HN;
            const float2 nk = *reinterpret_cast<const float2*>(Kn + pa + j0);
            const float2 nq = *reinterpret_cast<const float2*>(Qp + pa + j0);
            const float  nv = Vp[pa + i];
            const float  nb = Bp[pa + i];

            const float k0 = pk[u].x, k1 = pk[u].y;

            // dual interleaved butterflies over the 16-lane row group:
            // current S·kn and previous step's S·q
            float uu = fmaf(S1, k1, S0 * k0);
            float sv = sqp;
#pragma unroll
            for (int o = 1; o < 16; o <<= 1) {
                uu += __shfl_xor_sync(0xffffffffu, uu, o);
                sv += __shfl_xor_sync(0xffffffffu, sv, o);
            }
            // lazy store of previous step's output: out = sv^2 * sigmoid(sv)
            if (tcur > 0 && (l & 15) == 0)
                cell[base - HN + i] = sv * sv * __fdividef(1.f, 1.f + __expf(-sv));

            // state update: S_j = tanh(b_i*S_j + (v_i - r)*kn_j)
            const float delta = pv[u] - uu;
            const float bi    = pb[u];
            const float z0 = fmaf(bi, S0, delta * k0);
            const float z1 = fmaf(bi, S1, delta * k1);
            const float e0 = __expf(2.f * z0);
            const float e1 = __expf(2.f * z1);
            S0 = 1.f - __fdividef(2.f, e0 + 1.f);
            S1 = 1.f - __fdividef(2.f, e1 + 1.f);

            sqp = fmaf(S1, pq[u].y, S0 * pq[u].x);

            pk[u] = nk; pq[u] = nq; pv[u] = nv; pb[u] = nb;
            base += HN;
        }
    }

    // final step's output
    float sv = sqp;
#pragma unroll
    for (int o = 1; o < 16; o <<= 1) sv += __shfl_xor_sync(0xffffffffu, sv, o);
    if ((l & 15) == 0)
        cell[base - HN + i] = sv * sv * __fdividef(1.f, 1.f + __expf(-sv));

    if (writeS) {
        S_final[((size_t)chain * NN + i) * NN + j0]     = S0;
        S_final[((size_t)chain * NN + i) * NN + j0 + 1] = S1;
    }
}

// ---------------------------------------------------------------------------
// Host launcher
// ---------------------------------------------------------------------------
extern "C" void kernel_launch(void* const* d_in, const int* in_sizes, int n_in,
                              void* d_out, int out_size)
{
    const float* x      = (const float*)d_in[0];
    const float* W_in   = (const float*)d_in[1];
    const float* W_k    = (const float*)d_in[2];
    const float* W_v    = (const float*)d_in[3];
    const float* W_q    = (const float*)d_in[4];
    const float* W_beta = (const float*)d_in[5];
    const float* b_beta = (const float*)d_in[6];
    const float* W_out  = (const float*)d_in[7];
    float* y = (float*)d_out;

    float *xp, *k, *v, *q, *bt, *cell;
    cudaGetSymbolAddress((void**)&xp,   g_xp);
    cudaGetSymbolAddress((void**)&k,    g_k);
    cudaGetSymbolAddress((void**)&v,    g_v);
    cudaGetSymbolAddress((void**)&q,    g_q);
    cudaGetSymbolAddress((void**)&bt,   g_beta);
    cudaGetSymbolAddress((void**)&cell, g_cell);

    const int M = MROWS;

    // 1. xp = silu(x @ W_in^T)
    gemm_awt<1><<<dim3(DD / 128, M / 128), 256>>>(x, W_in, xp, nullptr, DD, DD);

    // 2. fused projections: k (normalized in epilogue), v, q, beta
    ProjPtrs p;
    p.W[0] = W_k;  p.W[1] = W_v;  p.W[2] = W_q;  p.W[3] = W_beta;
    p.C[0] = k;    p.C[1] = v;    p.C[2] = q;    p.C[3] = bt;
    gemm_proj4<<<dim3(HN / 128, M / 128, 4), 256>>>(xp, p, b_beta, HN, DD);

    // 3. sequential scan (16 warps per chain, 2 rows/warp)
    const size_t y_elems = (size_t)M * DD;
    const int writeS = (out_size >= (int)(y_elems + (size_t)BB * HH * NN * NN)) ? 1 : 0;
    scan_kernel<<<256, 128>>>(k, v, q, bt, cell, y + y_elems, writeS);

    // 4. y = cell @ W_out^T
    gemm_awt<0><<<dim3(DD / 128, M / 128), 256>>>(cell, W_out, y, nullptr, DD, HN);
}

// round 9
// speedup vs baseline: 1.3653x; 1.0181x over previous
#include <cuda_runtime.h>
#include <cstddef>
#include <cstdint>

// Problem constants
#define BB 8
#define TT 2048
#define DD 1024
#define HH 8
#define NN 32
#define MROWS (BB*TT)          // 16384
#define HN (HH*NN)             // 256

// ---------------------------------------------------------------------------
// Scratch (no cudaMalloc allowed) — __device__ globals.
// Split planes are stored as packed bf16 pairs (one u32 = 2 bf16 along K).
// ---------------------------------------------------------------------------
__device__ unsigned g_xh [(size_t)MROWS * DD / 2];   // x hi/lo
__device__ unsigned g_xl [(size_t)MROWS * DD / 2];
__device__ unsigned g_xph[(size_t)MROWS * DD / 2];   // xp = silu(in-proj) hi/lo
__device__ unsigned g_xpl[(size_t)MROWS * DD / 2];
__device__ unsigned g_wih[(size_t)DD * DD / 2];      // W_in
__device__ unsigned g_wil[(size_t)DD * DD / 2];
__device__ unsigned g_wkh[(size_t)HN * DD / 2];      // W_k/v/q/beta
__device__ unsigned g_wkl[(size_t)HN * DD / 2];
__device__ unsigned g_wvh[(size_t)HN * DD / 2];
__device__ unsigned g_wvl[(size_t)HN * DD / 2];
__device__ unsigned g_wqh[(size_t)HN * DD / 2];
__device__ unsigned g_wql[(size_t)HN * DD / 2];
__device__ unsigned g_wbh[(size_t)HN * DD / 2];
__device__ unsigned g_wbl[(size_t)HN * DD / 2];
__device__ unsigned g_woh[(size_t)DD * HN / 2];      // W_out
__device__ unsigned g_wol[(size_t)DD * HN / 2];
__device__ float    g_k   [(size_t)MROWS * HN];      // scan inputs (fp32)
__device__ float    g_v   [(size_t)MROWS * HN];
__device__ float    g_q   [(size_t)MROWS * HN];
__device__ float    g_beta[(size_t)MROWS * HN];
__device__ unsigned short g_cellh[(size_t)MROWS * HN];  // cell hi/lo bf16
__device__ unsigned short g_celll[(size_t)MROWS * HN];

// ---------------------------------------------------------------------------
// bf16 split helpers
// ---------------------------------------------------------------------------
__device__ __forceinline__ float trunc_hi(float x) {
    return __uint_as_float(__float_as_uint(x) & 0xFFFF0000u);
}
__device__ __forceinline__ unsigned pack_hi_pair(float e0, float e1) {
    return __byte_perm(__float_as_uint(e0), __float_as_uint(e1), 0x7632);
}
__device__ __forceinline__ unsigned pack_lo_pair(float l0, float l1) {
    unsigned d;
    asm("cvt.rn.bf16x2.f32 %0, %1, %2;" : "=r"(d) : "f"(l1), "f"(l0));
    return d;
}

__device__ __forceinline__ void mma_bf16(float d[4],
                                         unsigned a0, unsigned a1,
                                         unsigned a2, unsigned a3,
                                         unsigned b0, unsigned b1) {
    asm("mma.sync.aligned.m16n8k16.row.col.f32.bf16.bf16.f32 "
        "{%0,%1,%2,%3}, {%4,%5,%6,%7}, {%8,%9}, {%0,%1,%2,%3};"
        : "+f"(d[0]), "+f"(d[1]), "+f"(d[2]), "+f"(d[3])
        : "r"(a0), "r"(a1), "r"(a2), "r"(a3), "r"(b0), "r"(b1));
}

__device__ __forceinline__ void ldsm4(unsigned& r0, unsigned& r1,
                                      unsigned& r2, unsigned& r3, unsigned addr) {
    asm volatile("ldmatrix.sync.aligned.m8n8.x4.shared.b16 {%0,%1,%2,%3}, [%4];"
                 : "=r"(r0), "=r"(r1), "=r"(r2), "=r"(r3) : "r"(addr));
}

// ---------------------------------------------------------------------------
// Split kernel: fp32 pairs -> (hi bf16 pair word, lo bf16 pair word)
// ---------------------------------------------------------------------------
__global__ void __launch_bounds__(256)
split_kernel(const float2* __restrict__ in, unsigned* __restrict__ hi,
             unsigned* __restrict__ lo, int n)
{
    const int i = blockIdx.x * 256 + threadIdx.x;
    if (i < n) {
        const float2 v = in[i];
        hi[i] = pack_hi_pair(v.x, v.y);
        lo[i] = pack_lo_pair(v.x - trunc_hi(v.x), v.y - trunc_hi(v.y));
    }
}

// ---------------------------------------------------------------------------
// bf16x2-compensated tensor GEMM on pre-split operands.
// C = epi( A @ W^T ), A: [M][Kw] u32 (2 bf16/word), W: [Nout][Kw].
// Block 128x128, chunk k16 (8 words), 8 warps (2Mx4N), warp tile 64x32.
// Mainloop: 12 ldmatrix.x4 + 48 HMMA per warp per chunk.
// epi: 0 identity(fp32 C), 2 sigmoid(acc+bias)(fp32), 3 head-band row-norm(fp32),
//      4 silu + split-write to (Chi, Clo)
// ---------------------------------------------------------------------------
#define PLW 12
#define PLANE (128 * PLW)

__device__ __forceinline__ void mma_gemm_core(
    const unsigned* __restrict__ Ah, const unsigned* __restrict__ Al,
    const unsigned* __restrict__ Wh, const unsigned* __restrict__ Wl,
    float* __restrict__ C, unsigned* __restrict__ Chi, unsigned* __restrict__ Clo,
    const float* __restrict__ bias,
    int epi, int Nout, int Kw, int row0, int col0)
{
    // planes: 0 A_hi, 1 A_lo, 2 W_hi, 3 W_lo
    __shared__ unsigned sm[2][4 * PLANE];

    const int tid  = threadIdx.x;
    const int wid  = tid >> 5;
    const int lane = tid & 31;
    const int g    = lane >> 2;
    const int c    = lane & 3;
    const int wm   = (wid & 1) * 64;
    const int wn   = (wid >> 1) * 32;

    // staging: thread covers row lr, word-half wsel of each 8-word chunk row
    const int lr   = tid >> 1;
    const int wsel = tid & 1;
    const unsigned* Aph = Ah + (size_t)(row0 + lr) * Kw + wsel * 4;
    const unsigned* Apl = Al + (size_t)(row0 + lr) * Kw + wsel * 4;
    const unsigned* Wph = Wh + (size_t)(col0 + lr) * Kw + wsel * 4;
    const unsigned* Wpl = Wl + (size_t)(col0 + lr) * Kw + wsel * 4;
    const int srow = lr * PLW + wsel * 4;

    const unsigned smb = (unsigned)__cvta_generic_to_shared(&sm[0][0]);
    // ldmatrix lane-address offsets (bytes within a plane)
    const unsigned aoff = (((lane & 15) * PLW) + ((lane >> 4) << 2)) * 4;
    const unsigned boff = ((((lane >> 4) * 8 + (lane & 7)) * PLW) + ((lane & 8) ? 4 : 0)) * 4;

    float acc[4][4][4];
#pragma unroll
    for (int mt = 0; mt < 4; ++mt)
#pragma unroll
        for (int nt = 0; nt < 4; ++nt)
#pragma unroll
            for (int e = 0; e < 4; ++e) acc[mt][nt][e] = 0.f;

    const int nchunks = Kw / 8;

    // prologue: stage chunk 0 into buffer 0
    *reinterpret_cast<uint4*>(&sm[0][0 * PLANE + srow]) = *reinterpret_cast<const uint4*>(Aph);
    *reinterpret_cast<uint4*>(&sm[0][1 * PLANE + srow]) = *reinterpret_cast<const uint4*>(Apl);
    *reinterpret_cast<uint4*>(&sm[0][2 * PLANE + srow]) = *reinterpret_cast<const uint4*>(Wph);
    *reinterpret_cast<uint4*>(&sm[0][3 * PLANE + srow]) = *reinterpret_cast<const uint4*>(Wpl);
    __syncthreads();

    for (int chunk = 0; chunk < nchunks; ++chunk) {
        const int cur = chunk & 1;
        const bool more = (chunk + 1 < nchunks);

        uint4 fah, fal, fwh, fwl;
        if (more) {
            const int ko = (chunk + 1) * 8;
            fah = *reinterpret_cast<const uint4*>(Aph + ko);
            fal = *reinterpret_cast<const uint4*>(Apl + ko);
            fwh = *reinterpret_cast<const uint4*>(Wph + ko);
            fwl = *reinterpret_cast<const uint4*>(Wpl + ko);
        }

        const unsigned pb = smb + (unsigned)cur * (4 * PLANE * 4);

        // B fragments: 2 nt-pairs x (hi, lo)
        unsigned bh[2][4], bl[2][4];
#pragma unroll
        for (int pr = 0; pr < 2; ++pr) {
            const unsigned ba = pb + 2 * PLANE * 4 + (unsigned)(wn + pr * 16) * PLW * 4 + boff;
            ldsm4(bh[pr][0], bh[pr][1], bh[pr][2], bh[pr][3], ba);
            ldsm4(bl[pr][0], bl[pr][1], bl[pr][2], bl[pr][3], ba + PLANE * 4);
        }

#pragma unroll
        for (int mh = 0; mh < 2; ++mh) {
            unsigned ah[2][4], al[2][4];
#pragma unroll
            for (int m2 = 0; m2 < 2; ++m2) {
                const int rb = wm + (mh * 2 + m2) * 16;
                const unsigned aa = pb + (unsigned)rb * PLW * 4 + aoff;
                ldsm4(ah[m2][0], ah[m2][1], ah[m2][2], ah[m2][3], aa);
                ldsm4(al[m2][0], al[m2][1], al[m2][2], al[m2][3], aa + PLANE * 4);
            }
#pragma unroll
            for (int nt = 0; nt < 4; ++nt) {
                const unsigned b0 = bh[nt >> 1][(nt & 1) * 2];
                const unsigned b1 = bh[nt >> 1][(nt & 1) * 2 + 1];
                const unsigned c0 = bl[nt >> 1][(nt & 1) * 2];
                const unsigned c1 = bl[nt >> 1][(nt & 1) * 2 + 1];
#pragma unroll
                for (int m2 = 0; m2 < 2; ++m2) {
                    float* d = acc[mh * 2 + m2][nt];
                    mma_bf16(d, ah[m2][0], ah[m2][1], ah[m2][2], ah[m2][3], b0, b1); // hh
                    mma_bf16(d, al[m2][0], al[m2][1], al[m2][2], al[m2][3], b0, b1); // lh
                    mma_bf16(d, ah[m2][0], ah[m2][1], ah[m2][2], ah[m2][3], c0, c1); // hl
                }
            }
        }

        if (more) {
            const int nxt = cur ^ 1;
            *reinterpret_cast<uint4*>(&sm[nxt][0 * PLANE + srow]) = fah;
            *reinterpret_cast<uint4*>(&sm[nxt][1 * PLANE + srow]) = fal;
            *reinterpret_cast<uint4*>(&sm[nxt][2 * PLANE + srow]) = fwh;
            *reinterpret_cast<uint4*>(&sm[nxt][3 * PLANE + srow]) = fwl;
        }
        __syncthreads();
    }

    if (epi == 3) {
        // k-projection: normalize each row's 32-col head band (warp band = head)
#pragma unroll
        for (int mt = 0; mt < 4; ++mt) {
            float se = 0.f, so = 0.f;
#pragma unroll
            for (int nt = 0; nt < 4; ++nt) {
                se = fmaf(acc[mt][nt][0], acc[mt][nt][0], se);
                se = fmaf(acc[mt][nt][1], acc[mt][nt][1], se);
                so = fmaf(acc[mt][nt][2], acc[mt][nt][2], so);
                so = fmaf(acc[mt][nt][3], acc[mt][nt][3], so);
            }
            se += __shfl_xor_sync(0xffffffffu, se, 1);
            se += __shfl_xor_sync(0xffffffffu, se, 2);
            so += __shfl_xor_sync(0xffffffffu, so, 1);
            so += __shfl_xor_sync(0xffffffffu, so, 2);
            const float ie = __fdividef(1.f, sqrtf(se) + 1e-6f);
            const float io = __fdividef(1.f, sqrtf(so) + 1e-6f);
            const int r0 = row0 + wm + mt * 16 + g;
#pragma unroll
            for (int nt = 0; nt < 4; ++nt) {
                const int cc = col0 + wn + nt * 8 + 2 * c;
                *reinterpret_cast<float2*>(C + (size_t)r0 * Nout + cc) =
                    make_float2(acc[mt][nt][0] * ie, acc[mt][nt][1] * ie);
                *reinterpret_cast<float2*>(C + (size_t)(r0 + 8) * Nout + cc) =
                    make_float2(acc[mt][nt][2] * io, acc[mt][nt][3] * io);
            }
        }
        return;
    }

#pragma unroll
    for (int mt = 0; mt < 4; ++mt) {
        const int r0 = row0 + wm + mt * 16 + g;
#pragma unroll
        for (int nt = 0; nt < 4; ++nt) {
            const int cc = col0 + wn + nt * 8 + 2 * c;
            float d0 = acc[mt][nt][0], d1 = acc[mt][nt][1];
            float d2 = acc[mt][nt][2], d3 = acc[mt][nt][3];
            if (epi == 4) {
                // silu then split-write hi/lo planes
                d0 = d0 * __fdividef(1.f, 1.f + __expf(-d0));
                d1 = d1 * __fdividef(1.f, 1.f + __expf(-d1));
                d2 = d2 * __fdividef(1.f, 1.f + __expf(-d2));
                d3 = d3 * __fdividef(1.f, 1.f + __expf(-d3));
                const size_t w0 = ((size_t)r0 * Nout + cc) >> 1;
                const size_t w1 = ((size_t)(r0 + 8) * Nout + cc) >> 1;
                Chi[w0] = pack_hi_pair(d0, d1);
                Clo[w0] = pack_lo_pair(d0 - trunc_hi(d0), d1 - trunc_hi(d1));
                Chi[w1] = pack_hi_pair(d2, d3);
                Clo[w1] = pack_lo_pair(d2 - trunc_hi(d2), d3 - trunc_hi(d3));
                continue;
            }
            if (epi == 2) {
                const float b0 = bias[cc], b1 = bias[cc + 1];
                d0 = __fdividef(1.f, 1.f + __expf(-(d0 + b0)));
                d1 = __fdividef(1.f, 1.f + __expf(-(d1 + b1)));
                d2 = __fdividef(1.f, 1.f + __expf(-(d2 + b0)));
                d3 = __fdividef(1.f, 1.f + __expf(-(d3 + b1)));
            }
            *reinterpret_cast<float2*>(C + (size_t)r0 * Nout + cc)       = make_float2(d0, d1);
            *reinterpret_cast<float2*>(C + (size_t)(r0 + 8) * Nout + cc) = make_float2(d2, d3);
        }
    }
}

template<int EPI>
__global__ void __launch_bounds__(256, 2)
gemm_bf16(const unsigned* __restrict__ Ah, const unsigned* __restrict__ Al,
          const unsigned* __restrict__ Wh, const unsigned* __restrict__ Wl,
          float* __restrict__ C, unsigned* __restrict__ Chi, unsigned* __restrict__ Clo,
          const float* __restrict__ bias, int Nout, int Kw)
{
    mma_gemm_core(Ah, Al, Wh, Wl, C, Chi, Clo, bias, EPI, Nout, Kw,
                  blockIdx.y * 128, blockIdx.x * 128);
}

struct ProjPtrs {
    const unsigned* Wh[4];
    const unsigned* Wl[4];
    float*          C[4];
};

// z: 0 = k (head-band normalize), 1 = v, 2 = q, 3 = beta (sigmoid+bias)
__global__ void __launch_bounds__(256, 2)
gemm_proj4(const unsigned* __restrict__ Ah, const unsigned* __restrict__ Al,
           ProjPtrs p, const float* __restrict__ bias, int Nout, int Kw)
{
    const int z = blockIdx.z;
    const int epi = (z == 0) ? 3 : ((z == 3) ? 2 : 0);
    mma_gemm_core(Ah, Al, p.Wh[z], p.Wl[z], p.C[z], nullptr, nullptr, bias,
                  epi, Nout, Kw, blockIdx.y * 128, blockIdx.x * 128);
}

// ---------------------------------------------------------------------------
// Barrier-free sequential scan (round-8 tiling: 2 cols/lane, 2 rows/warp,
// 16 warps/chain). Writes cell output directly as split bf16 hi/lo planes.
// ---------------------------------------------------------------------------
#define PF 4

__global__ void __launch_bounds__(128)
scan_kernel(const float* __restrict__ Kn, const float* __restrict__ Vp,
            const float* __restrict__ Qp, const float* __restrict__ Bp,
            unsigned short* __restrict__ cellh, unsigned short* __restrict__ celll,
            float* __restrict__ S_final, int writeS)
{
    const int g     = blockIdx.x * 4 + (threadIdx.x >> 5);  // global warp 0..1023
    const int chain = g >> 4;                // 0..63
    const int wc    = g & 15;                // warp-in-chain 0..15
    const int l     = threadIdx.x & 31;
    const int i     = wc * 2 + (l >> 4);     // state row 0..31
    const int j0    = (l & 15) * 2;          // first state col of this lane
    const size_t cb = ((size_t)(chain >> 3) * TT) * HN + (size_t)(chain & 7) * NN;

    float2 pk[PF], pq[PF];
    float  pv[PF], pb[PF];
#pragma unroll
    for (int d = 0; d < PF; ++d) {
        const size_t a = cb + (size_t)d * HN;
        pk[d] = *reinterpret_cast<const float2*>(Kn + a + j0);
        pq[d] = *reinterpret_cast<const float2*>(Qp + a + j0);
        pv[d] = Vp[a + i];
        pb[d] = Bp[a + i];
    }

    float S0 = 0.f, S1 = 0.f, sqp = 0.f;
    size_t base = cb;

    for (int t = 0; t < TT; t += PF) {
#pragma unroll
        for (int u = 0; u < PF; ++u) {
            const int tcur = t + u;
            const int tpre = (tcur + PF < TT) ? (tcur + PF) : (TT - 1);
            const size_t pa = cb + (size_t)tpre * HN;
            const float2 nk = *reinterpret_cast<const float2*>(Kn + pa + j0);
            const float2 nq = *reinterpret_cast<const float2*>(Qp + pa + j0);
            const float  nv = Vp[pa + i];
            const float  nb = Bp[pa + i];

            const float k0 = pk[u].x, k1 = pk[u].y;

            float uu = fmaf(S1, k1, S0 * k0);
            float sv = sqp;
#pragma unroll
            for (int o = 1; o < 16; o <<= 1) {
                uu += __shfl_xor_sync(0xffffffffu, uu, o);
                sv += __shfl_xor_sync(0xffffffffu, sv, o);
            }
            if (tcur > 0 && (l & 15) == 0) {
                const float ov = sv * sv * __fdividef(1.f, 1.f + __expf(-sv));
                cellh[base - HN + i] = (unsigned short)(__float_as_uint(ov) >> 16);
                unsigned short lo16;
                const float res = ov - trunc_hi(ov);
                asm("cvt.rn.bf16.f32 %0, %1;" : "=h"(lo16) : "f"(res));
                celll[base - HN + i] = lo16;
            }

            const float delta = pv[u] - uu;
            const float bi    = pb[u];
            const float z0 = fmaf(bi, S0, delta * k0);
            const float z1 = fmaf(bi, S1, delta * k1);
            const float e0 = __expf(2.f * z0);
            const float e1 = __expf(2.f * z1);
            S0 = 1.f - __fdividef(2.f, e0 + 1.f);
            S1 = 1.f - __fdividef(2.f, e1 + 1.f);

            sqp = fmaf(S1, pq[u].y, S0 * pq[u].x);

            pk[u] = nk; pq[u] = nq; pv[u] = nv; pb[u] = nb;
            base += HN;
        }
    }

    float sv = sqp;
#pragma unroll
    for (int o = 1; o < 16; o <<= 1) sv += __shfl_xor_sync(0xffffffffu, sv, o);
    if ((l & 15) == 0) {
        const float ov = sv * sv * __fdividef(1.f, 1.f + __expf(-sv));
        cellh[base - HN + i] = (unsigned short)(__float_as_uint(ov) >> 16);
        unsigned short lo16;
        const float res = ov - trunc_hi(ov);
        asm("cvt.rn.bf16.f32 %0, %1;" : "=h"(lo16) : "f"(res));
        celll[base - HN + i] = lo16;
    }

    if (writeS) {
        S_final[((size_t)chain * NN + i) * NN + j0]     = S0;
        S_final[((size_t)chain * NN + i) * NN + j0 + 1] = S1;
    }
}

// ---------------------------------------------------------------------------
// Host launcher
// ---------------------------------------------------------------------------
extern "C" void kernel_launch(void* const* d_in, const int* in_sizes, int n_in,
                              void* d_out, int out_size)
{
    const float* x      = (const float*)d_in[0];
    const float* W_in   = (const float*)d_in[1];
    const float* W_k    = (const float*)d_in[2];
    const float* W_v    = (const float*)d_in[3];
    const float* W_q    = (const float*)d_in[4];
    const float* W_beta = (const float*)d_in[5];
    const float* b_beta = (const float*)d_in[6];
    const float* W_out  = (const float*)d_in[7];
    float* y = (float*)d_out;

    unsigned *xh, *xl, *xph, *xpl, *wih, *wil;
    unsigned *wkh, *wkl, *wvh, *wvl, *wqh, *wql, *wbh, *wbl, *woh, *wol;
    float *k, *v, *q, *bt;
    unsigned short *cellh, *celll;
    cudaGetSymbolAddress((void**)&xh,  g_xh);  cudaGetSymbolAddress((void**)&xl,  g_xl);
    cudaGetSymbolAddress((void**)&xph, g_xph); cudaGetSymbolAddress((void**)&xpl, g_xpl);
    cudaGetSymbolAddress((void**)&wih, g_wih); cudaGetSymbolAddress((void**)&wil, g_wil);
    cudaGetSymbolAddress((void**)&wkh, g_wkh); cudaGetSymbolAddress((void**)&wkl, g_wkl);
    cudaGetSymbolAddress((void**)&wvh, g_wvh); cudaGetSymbolAddress((void**)&wvl, g_wvl);
    cudaGetSymbolAddress((void**)&wqh, g_wqh); cudaGetSymbolAddress((void**)&wql, g_wql);
    cudaGetSymbolAddress((void**)&wbh, g_wbh); cudaGetSymbolAddress((void**)&wbl, g_wbl);
    cudaGetSymbolAddress((void**)&woh, g_woh); cudaGetSymbolAddress((void**)&wol, g_wol);
    cudaGetSymbolAddress((void**)&k,  g_k);  cudaGetSymbolAddress((void**)&v,  g_v);
    cudaGetSymbolAddress((void**)&q,  g_q);  cudaGetSymbolAddress((void**)&bt, g_beta);
    cudaGetSymbolAddress((void**)&cellh, g_cellh);
    cudaGetSymbolAddress((void**)&celll, g_celll);

    const int M = MROWS;

    // 0. split fp32 operands into bf16 hi/lo planes
    split_kernel<<<(M * DD / 2) / 256, 256>>>((const float2*)x, xh, xl, M * DD / 2);
    split_kernel<<<(DD * DD / 2) / 256, 256>>>((const float2*)W_in, wih, wil, DD * DD / 2);
    split_kernel<<<(HN * DD / 2) / 256, 256>>>((const float2*)W_k, wkh, wkl, HN * DD / 2);
    split_kernel<<<(HN * DD / 2) / 256, 256>>>((const float2*)W_v, wvh, wvl, HN * DD / 2);
    split_kernel<<<(HN * DD / 2) / 256, 256>>>((const float2*)W_q, wqh, wql, HN * DD / 2);
    split_kernel<<<(HN * DD / 2) / 256, 256>>>((const float2*)W_beta, wbh, wbl, HN * DD / 2);
    split_kernel<<<(DD * HN / 2) / 256, 256>>>((const float2*)W_out, woh, wol, DD * HN / 2);

    // 1. xp = silu(x @ W_in^T), written directly as split planes (epi 4)
    gemm_bf16<4><<<dim3(DD / 128, M / 128), 256>>>(xh, xl, wih, wil,
                                                   nullptr, xph, xpl, nullptr,
                                                   DD, DD / 2);

    // 2. fused projections: k (normalized), v, q, beta
    ProjPtrs p;
    p.Wh[0] = wkh; p.Wl[0] = wkl; p.C[0] = k;
    p.Wh[1] = wvh; p.Wl[1] = wvl; p.C[1] = v;
    p.Wh[2] = wqh; p.Wl[2] = wql; p.C[2] = q;
    p.Wh[3] = wbh; p.Wl[3] = wbl; p.C[3] = bt;
    gemm_proj4<<<dim3(HN / 128, M / 128, 4), 256>>>(xph, xpl, p, b_beta, HN, DD / 2);

    // 3. sequential scan (writes cell as split bf16 planes)
    const size_t y_elems = (size_t)M * DD;
    const int writeS = (out_size >= (int)(y_elems + (size_t)BB * HH * NN * NN)) ? 1 : 0;
    scan_kernel<<<256, 128>>>(k, v, q, bt, cellh, celll, y + y_elems, writeS);

    // 4. y = cell @ W_out^T
    gemm_bf16<0><<<dim3(DD / 128, M / 128), 256>>>(
        (const unsigned*)cellh, (const unsigned*)celll, woh, wol,
        y, nullptr, nullptr, nullptr, DD, HN / 2);
}